// round 1
// baseline (speedup 1.0000x reference)
#include <cuda_runtime.h>
#include <math.h>

#define BATCH 2048
#define BN_INV 0.9999950000374997f   // 1/sqrt(1+1e-5)

// ---------------- scratch (static device globals; no runtime allocation) ----
__device__ float g_h1[BATCH * 32 * 12 * 12];   // after stage1: 37.7 MB
__device__ float g_h2[BATCH * 1024];           // after stage2 (flattened)
__device__ float g_fc1[BATCH * 512];           // raw fc1 output (pre-ternarize)

// ---------------- block reduction helper ------------------------------------
__device__ __forceinline__ float block_reduce(float v, float* s_red, int tid, int nthr) {
    #pragma unroll
    for (int o = 16; o > 0; o >>= 1) v += __shfl_down_sync(0xffffffffu, v, o);
    int wid = tid >> 5, lane = tid & 31, nw = nthr >> 5;
    __syncthreads();                    // protect s_red from previous round
    if (lane == 0) s_red[wid] = v;
    __syncthreads();
    if (wid == 0) {
        float x = (lane < nw) ? s_red[lane] : 0.f;
        #pragma unroll
        for (int o = 16; o > 0; o >>= 1) x += __shfl_down_sync(0xffffffffu, x, o);
        if (lane == 0) s_red[0] = x;
    }
    __syncthreads();
    return s_red[0];
}

// ============================================================================
// K1: conv1 (1->32, 5x5, 28->24) + ternarize(per-sample) + BN + maxpool + relu
// one CTA per sample, 256 threads
// smem: in 28x29 pad (812) | w 800 | b 32 | out 32x577 pad (18464) | red 16
// ============================================================================
#define K1_SMEM ((812 + 800 + 32 + 18464 + 16) * 4)

__global__ __launch_bounds__(256) void k1_conv1(
    const float* __restrict__ x, const float* __restrict__ w,
    const float* __restrict__ bias, const float* __restrict__ bng,
    const float* __restrict__ bnb)
{
    extern __shared__ float sm[];
    float* s_in  = sm;             // [28][29]
    float* s_w   = s_in + 812;     // [32*25]
    float* s_b   = s_w + 800;      // [32]
    float* s_out = s_b + 32;       // [32][577] (576 used)
    float* s_red = s_out + 18464;  // [16]

    const int tid = threadIdx.x;
    const int s = blockIdx.x;

    const float* xin = x + s * 784;
    for (int i = tid; i < 784; i += 256) s_in[(i / 28) * 29 + (i % 28)] = xin[i];
    for (int i = tid; i < 800; i += 256) s_w[i] = w[i];
    if (tid < 32) s_b[tid] = bias[tid];
    __syncthreads();

    // each thread computes 3 full output rows (oc, oy); warp-uniform oy,
    // lane-varying oc (weight LDS stride 25 -> conflict-free; input broadcast)
    float sumabs = 0.f;
    #pragma unroll
    for (int t = 0; t < 3; t++) {
        const int idx = tid + 256 * t;      // 0..767
        const int oy = idx >> 5;            // 0..23
        const int oc = idx & 31;            // 0..31
        float acc[24];
        const float bb = s_b[oc];
        #pragma unroll
        for (int i = 0; i < 24; i++) acc[i] = bb;
        #pragma unroll
        for (int ky = 0; ky < 5; ky++) {
            float rowv[28];
            const float* rp = s_in + (oy + ky) * 29;
            #pragma unroll
            for (int c = 0; c < 28; c++) rowv[c] = rp[c];
            #pragma unroll
            for (int kx = 0; kx < 5; kx++) {
                const float wv = s_w[oc * 25 + ky * 5 + kx];
                #pragma unroll
                for (int ox = 0; ox < 24; ox++)
                    acc[ox] = fmaf(rowv[ox + kx], wv, acc[ox]);
            }
        }
        float* op = s_out + oc * 577 + oy * 24;
        #pragma unroll
        for (int ox = 0; ox < 24; ox++) { op[ox] = acc[ox]; sumabs += fabsf(acc[ox]); }
    }

    const float tot   = block_reduce(sumabs, s_red, tid, 256);
    const float delta = 0.7f * tot / 18432.f;

    float ms = 0.f, cnt = 0.f;
    for (int i = tid; i < 18432; i += 256) {
        const float v = s_out[(i / 576) * 577 + (i % 576)];
        const float a = fabsf(v);
        if (a > delta) { ms += a; cnt += 1.f; }
    }
    ms  = block_reduce(ms,  s_red, tid, 256);
    cnt = block_reduce(cnt, s_red, tid, 256);
    const float alpha = ms / cnt;

    // ternarize + BN + 2x2 maxpool + relu -> g_h1 [s][32][12][12]
    for (int i = tid; i < 4608; i += 256) {
        const int oc = i / 144, r = i % 144, py = r / 12, px = r % 12;
        const float* bp = s_out + oc * 577 + (2 * py) * 24 + 2 * px;
        const float g = bng[oc] * BN_INV, bb2 = bnb[oc];
        float m = -INFINITY;
        #pragma unroll
        for (int dy = 0; dy < 2; dy++)
            #pragma unroll
            for (int dx = 0; dx < 2; dx++) {
                const float v  = bp[dy * 24 + dx];
                const float tv = (v > delta) ? alpha : ((v < -delta) ? -alpha : 0.f);
                m = fmaxf(m, fmaf(tv, g, bb2));
            }
        g_h1[s * 4608 + i] = fmaxf(m, 0.f);
    }
}

// ============================================================================
// K2: conv2 (32->64, 5x5, 12->8) + ternarize + BN + maxpool + relu
// one CTA per sample, 256 threads; weights staged in 2 chunks of 32 oc
// smem: in 4608 | out 64x65 pad (4160) | w 32x801 pad (25632) | red 16
// ============================================================================
#define K2_SMEM ((4608 + 4160 + 25632 + 16) * 4)

__global__ __launch_bounds__(256) void k2_conv2(
    const float* __restrict__ w, const float* __restrict__ bias,
    const float* __restrict__ bng, const float* __restrict__ bnb)
{
    extern __shared__ float sm[];
    float* s_in  = sm;             // [32][12][12]
    float* s_out = s_in + 4608;    // [64][65] (64 used)
    float* s_w   = s_out + 4160;   // [32][801] (800 used)
    float* s_red = s_w + 25632;    // [16]

    const int tid = threadIdx.x;
    const int s = blockIdx.x;
    const int oy = tid >> 5;       // 0..7 (warp-uniform)
    const int oc_l = tid & 31;     // 0..31 (lane)

    const float* hin = g_h1 + s * 4608;
    for (int i = tid; i < 4608; i += 256) s_in[i] = hin[i];

    float sumabs = 0.f;
    for (int c = 0; c < 2; c++) {
        __syncthreads();           // s_in ready / previous chunk compute done
        for (int i = tid; i < 25600; i += 256) {
            const int ol = i / 800, rem = i % 800;
            s_w[ol * 801 + rem] = w[(c * 32 + ol) * 800 + rem];
        }
        __syncthreads();

        const int oc = c * 32 + oc_l;
        float acc[8];
        const float bb = bias[oc];
        #pragma unroll
        for (int i = 0; i < 8; i++) acc[i] = bb;

        for (int ic = 0; ic < 32; ic++) {
            #pragma unroll
            for (int ky = 0; ky < 5; ky++) {
                float rowv[12];
                const float* rp = s_in + ic * 144 + (oy + ky) * 12;
                #pragma unroll
                for (int i2 = 0; i2 < 12; i2++) rowv[i2] = rp[i2];
                const float* wp = s_w + oc_l * 801 + ic * 25 + ky * 5;
                #pragma unroll
                for (int kx = 0; kx < 5; kx++) {
                    const float wv = wp[kx];
                    #pragma unroll
                    for (int ox = 0; ox < 8; ox++)
                        acc[ox] = fmaf(rowv[ox + kx], wv, acc[ox]);
                }
            }
        }
        float* op = s_out + oc * 65 + oy * 8;
        #pragma unroll
        for (int ox = 0; ox < 8; ox++) { op[ox] = acc[ox]; sumabs += fabsf(acc[ox]); }
    }

    const float tot   = block_reduce(sumabs, s_red, tid, 256);
    const float delta = 0.7f * tot / 4096.f;

    float ms = 0.f, cnt = 0.f;
    for (int i = tid; i < 4096; i += 256) {
        const float v = s_out[(i >> 6) * 65 + (i & 63)];
        const float a = fabsf(v);
        if (a > delta) { ms += a; cnt += 1.f; }
    }
    ms  = block_reduce(ms,  s_red, tid, 256);
    cnt = block_reduce(cnt, s_red, tid, 256);
    const float alpha = ms / cnt;

    // ternarize + BN + maxpool + relu -> g_h2 [s][1024] (c*16 + y*4 + x)
    for (int i = tid; i < 1024; i += 256) {
        const int oc = i >> 4, r = i & 15, py = r >> 2, px = r & 3;
        const float* bp = s_out + oc * 65 + (2 * py) * 8 + 2 * px;
        const float g = bng[oc] * BN_INV, bb2 = bnb[oc];
        float m = -INFINITY;
        #pragma unroll
        for (int dy = 0; dy < 2; dy++)
            #pragma unroll
            for (int dx = 0; dx < 2; dx++) {
                const float v  = bp[dy * 8 + dx];
                const float tv = (v > delta) ? alpha : ((v < -delta) ? -alpha : 0.f);
                m = fmaxf(m, fmaf(tv, g, bb2));
            }
        g_h2[s * 1024 + i] = fmaxf(m, 0.f);
    }
}

// ============================================================================
// K3: fc1 GEMM  g_fc1[2048,512] = g_h2[2048,1024] @ fc1_w[512,1024]^T + b
// 64x64 CTA tile, Ktile=16, 256 threads, 4x4 microtile
// ============================================================================
__global__ __launch_bounds__(256) void k3_fc1(
    const float* __restrict__ Wf, const float* __restrict__ bf)
{
    __shared__ float As[16 * 68];  // [k][m], padded stride 68
    __shared__ float Bs[16 * 68];  // [k][n]

    const int tid = threadIdx.x;
    const int tx = tid & 15, ty = tid >> 4;
    const int bn = blockIdx.x, bm = blockIdx.y;

    const float* Ap = g_h2 + (size_t)(bm * 64) * 1024;
    const float* Bp = Wf   + (size_t)(bn * 64) * 1024;

    const int lr = tid >> 2;            // row 0..63 within tile
    const int lk = (tid & 3) * 4;       // k offset 0,4,8,12

    float acc[4][4] = {};

    for (int k0 = 0; k0 < 1024; k0 += 16) {
        const float4 a = *(const float4*)(Ap + lr * 1024 + k0 + lk);
        const float4 b = *(const float4*)(Bp + lr * 1024 + k0 + lk);
        __syncthreads();   // previous tile consumed
        As[(lk + 0) * 68 + lr] = a.x; As[(lk + 1) * 68 + lr] = a.y;
        As[(lk + 2) * 68 + lr] = a.z; As[(lk + 3) * 68 + lr] = a.w;
        Bs[(lk + 0) * 68 + lr] = b.x; Bs[(lk + 1) * 68 + lr] = b.y;
        Bs[(lk + 2) * 68 + lr] = b.z; Bs[(lk + 3) * 68 + lr] = b.w;
        __syncthreads();
        #pragma unroll
        for (int kk = 0; kk < 16; kk++) {
            const float4 av = *(const float4*)(&As[kk * 68 + ty * 4]);
            const float4 bv = *(const float4*)(&Bs[kk * 68 + tx * 4]);
            const float a4[4] = {av.x, av.y, av.z, av.w};
            const float b4[4] = {bv.x, bv.y, bv.z, bv.w};
            #pragma unroll
            for (int i = 0; i < 4; i++)
                #pragma unroll
                for (int j = 0; j < 4; j++)
                    acc[i][j] = fmaf(a4[i], b4[j], acc[i][j]);
        }
    }

    const int n0 = bn * 64 + tx * 4;
    const float4 bia = *(const float4*)(bf + n0);
    #pragma unroll
    for (int i = 0; i < 4; i++) {
        const int m = bm * 64 + ty * 4 + i;
        float4 o;
        o.x = acc[i][0] + bia.x; o.y = acc[i][1] + bia.y;
        o.z = acc[i][2] + bia.z; o.w = acc[i][3] + bia.w;
        *(float4*)(g_fc1 + (size_t)m * 512 + n0) = o;
    }
}

// ============================================================================
// K4: ternarize(512)+relu of fc1 row, then fc2 (10x512) + ternarize(10) -> out
// one CTA per sample, 512 threads
// ============================================================================
__global__ __launch_bounds__(512) void k4_fc2(
    const float* __restrict__ W2, const float* __restrict__ b2,
    float* __restrict__ out)
{
    __shared__ float s_w2[5120];
    __shared__ float s_red[32];
    __shared__ float s_part[16][10];
    __shared__ float s_o[10];

    const int tid = threadIdx.x;
    const int s = blockIdx.x;

    for (int i = tid; i < 5120; i += 512) s_w2[i] = W2[i];

    const float v = g_fc1[(size_t)s * 512 + tid];

    const float tot   = block_reduce(fabsf(v), s_red, tid, 512);
    const float delta = 0.7f * tot / 512.f;
    const float a = fabsf(v);
    float ms = (a > delta) ? a : 0.f;
    float ct = (a > delta) ? 1.f : 0.f;
    ms = block_reduce(ms, s_red, tid, 512);
    ct = block_reduce(ct, s_red, tid, 512);
    const float alpha = ms / ct;

    const float tv = (v > delta) ? alpha : ((v < -delta) ? -alpha : 0.f);
    const float h = fmaxf(tv, 0.f);

    // fc2: 10 dot products of length 512
    float p[10];
    #pragma unroll
    for (int j = 0; j < 10; j++) p[j] = h * s_w2[j * 512 + tid];
    #pragma unroll
    for (int j = 0; j < 10; j++) {
        float x = p[j];
        #pragma unroll
        for (int o = 16; o > 0; o >>= 1) x += __shfl_down_sync(0xffffffffu, x, o);
        if ((tid & 31) == 0) s_part[tid >> 5][j] = x;
    }
    __syncthreads();
    if (tid < 10) {
        float x = b2[tid];
        #pragma unroll
        for (int w = 0; w < 16; w++) x += s_part[w][tid];
        s_o[tid] = x;
    }
    __syncthreads();
    if (tid == 0) {
        float sa = 0.f;
        #pragma unroll
        for (int j = 0; j < 10; j++) sa += fabsf(s_o[j]);
        const float d2 = 0.7f * sa / 10.f;
        float ms2 = 0.f, c2 = 0.f;
        #pragma unroll
        for (int j = 0; j < 10; j++) {
            const float aj = fabsf(s_o[j]);
            if (aj > d2) { ms2 += aj; c2 += 1.f; }
        }
        const float al2 = ms2 / c2;
        #pragma unroll
        for (int j = 0; j < 10; j++) {
            const float oj = s_o[j];
            out[(size_t)s * 10 + j] = (oj > d2) ? al2 : ((oj < -d2) ? -al2 : 0.f);
        }
    }
}

// ============================================================================
extern "C" void kernel_launch(void* const* d_in, const int* in_sizes, int n_in,
                              void* d_out, int out_size)
{
    const float* x       = (const float*)d_in[0];
    const float* conv1_w = (const float*)d_in[1];
    const float* conv1_b = (const float*)d_in[2];
    const float* bn1_g   = (const float*)d_in[3];
    const float* bn1_b   = (const float*)d_in[4];
    const float* conv2_w = (const float*)d_in[5];
    const float* conv2_b = (const float*)d_in[6];
    const float* bn2_g   = (const float*)d_in[7];
    const float* bn2_b   = (const float*)d_in[8];
    const float* fc1_w   = (const float*)d_in[9];
    const float* fc1_b   = (const float*)d_in[10];
    const float* fc2_w   = (const float*)d_in[11];
    const float* fc2_b   = (const float*)d_in[12];
    float* out = (float*)d_out;

    cudaFuncSetAttribute(k1_conv1, cudaFuncAttributeMaxDynamicSharedMemorySize, K1_SMEM);
    cudaFuncSetAttribute(k2_conv2, cudaFuncAttributeMaxDynamicSharedMemorySize, K2_SMEM);

    k1_conv1<<<BATCH, 256, K1_SMEM>>>(x, conv1_w, conv1_b, bn1_g, bn1_b);
    k2_conv2<<<BATCH, 256, K2_SMEM>>>(conv2_w, conv2_b, bn2_g, bn2_b);
    k3_fc1<<<dim3(8, 32), 256>>>(fc1_w, fc1_b);
    k4_fc2<<<BATCH, 512>>>(fc2_w, fc2_b, out);
}

// round 2
// speedup vs baseline: 1.5727x; 1.5727x over previous
#include <cuda_runtime.h>
#include <math.h>

#define BATCH 2048
#define BN_INV 0.9999950000374997f   // 1/sqrt(1+1e-5)

typedef unsigned long long u64;

// packed f32x2 helpers (exact fp32 semantics, 2x FFMA throughput on sm_103a)
#define FMA2(acc, a, b) asm("fma.rn.f32x2 %0, %1, %2, %0;" : "+l"(acc) : "l"(a), "l"(b))
__device__ __forceinline__ u64 pack2(float lo, float hi) {
    u64 r; asm("mov.b64 %0, {%1, %2};" : "=l"(r) : "f"(lo), "f"(hi)); return r;
}
__device__ __forceinline__ float2 unpack2(u64 v) {
    float2 f; asm("mov.b64 {%0, %1}, %2;" : "=f"(f.x), "=f"(f.y) : "l"(v)); return f;
}
__device__ __forceinline__ float ternv(float v, float delta, float alpha) {
    return (v > delta) ? alpha : ((v < -delta) ? -alpha : 0.f);
}

// ---------------- scratch ---------------------------------------------------
__device__ float g_h1[BATCH * 32 * 12 * 12];
__device__ float g_h2[BATCH * 1024];
__device__ float g_fc1[BATCH * 512];
__device__ u64   g_w2p[25600];     // conv2 weights, paired (oc, oc+32) layout

// ---------------- block reductions ------------------------------------------
__device__ __forceinline__ float block_reduce(float v, float* s_red, int tid, int nthr) {
    #pragma unroll
    for (int o = 16; o > 0; o >>= 1) v += __shfl_down_sync(0xffffffffu, v, o);
    int wid = tid >> 5, lane = tid & 31, nw = nthr >> 5;
    __syncthreads();
    if (lane == 0) s_red[wid] = v;
    __syncthreads();
    if (wid == 0) {
        float x = (lane < nw) ? s_red[lane] : 0.f;
        #pragma unroll
        for (int o = 16; o > 0; o >>= 1) x += __shfl_down_sync(0xffffffffu, x, o);
        if (lane == 0) s_red[0] = x;
    }
    __syncthreads();
    return s_red[0];
}

__device__ __forceinline__ float2 block_reduce2(float a, float b, float* s_red, int tid, int nthr) {
    #pragma unroll
    for (int o = 16; o > 0; o >>= 1) {
        a += __shfl_down_sync(0xffffffffu, a, o);
        b += __shfl_down_sync(0xffffffffu, b, o);
    }
    int wid = tid >> 5, lane = tid & 31, nw = nthr >> 5;
    __syncthreads();
    if (lane == 0) { s_red[wid] = a; s_red[32 + wid] = b; }
    __syncthreads();
    if (wid == 0) {
        float x = (lane < nw) ? s_red[lane] : 0.f;
        float y = (lane < nw) ? s_red[32 + lane] : 0.f;
        #pragma unroll
        for (int o = 16; o > 0; o >>= 1) {
            x += __shfl_down_sync(0xffffffffu, x, o);
            y += __shfl_down_sync(0xffffffffu, y, o);
        }
        if (lane == 0) { s_red[0] = x; s_red[32] = y; }
    }
    __syncthreads();
    float2 r; r.x = s_red[0]; r.y = s_red[32];
    return r;
}

// ============================================================================
// K0: repack conv2 weights into (oc, oc+32) pairs: g_w2p[(ic*25+pos)*32+ocl]
// ============================================================================
__global__ void k0_pack_w2(const float* __restrict__ w) {
    int i = blockIdx.x * 256 + threadIdx.x;
    if (i < 25600) {
        int icpos = i >> 5, ocl = i & 31;
        g_w2p[i] = pack2(w[ocl * 800 + icpos], w[(ocl + 32) * 800 + icpos]);
    }
}

// ============================================================================
// K1: conv1 + ternarize + BN + maxpool + relu. 1 CTA/sample, 384 threads.
// thread = (oy 0..23, ocl 0..15); accs = 24 ox as f32x2 over (ocl, ocl+16).
// ============================================================================
__global__ __launch_bounds__(384) void k1_conv1(
    const float* __restrict__ x, const float* __restrict__ w,
    const float* __restrict__ bias, const float* __restrict__ bng,
    const float* __restrict__ bnb)
{
    __shared__ float s_in[784];      // [28][28]
    __shared__ u64   s_w[400];       // [25 pos][16 ocl] pairs
    __shared__ u64   s_b[16];
    __shared__ float s_ex[9504];     // [(oy*12+px)][33] oc-indexed
    __shared__ float s_red[64];

    const int tid = threadIdx.x;
    const int s = blockIdx.x;
    const int ocl = tid & 15;
    const int oy  = tid >> 4;        // 0..23; warp has 2 oy values

    const float* xin = x + s * 784;
    for (int i = tid; i < 784; i += 384) s_in[i] = xin[i];
    for (int i = tid; i < 400; i += 384) {
        int pos = i >> 4, oc2 = i & 15;
        s_w[i] = pack2(w[oc2 * 25 + pos], w[(oc2 + 16) * 25 + pos]);
    }
    if (tid < 16) s_b[tid] = pack2(bias[tid], bias[tid + 16]);
    __syncthreads();

    u64 acc[24];
    {
        const u64 bb = s_b[ocl];
        #pragma unroll
        for (int p = 0; p < 24; p++) acc[p] = bb;
    }

    #pragma unroll
    for (int ky = 0; ky < 5; ky++) {
        const float* rp = s_in + (oy + ky) * 28;
        u64 rp2[28];
        #pragma unroll
        for (int t = 0; t < 7; t++) {
            const float4 q = *(const float4*)(rp + t * 4);
            rp2[t * 4 + 0] = pack2(q.x, q.x);
            rp2[t * 4 + 1] = pack2(q.y, q.y);
            rp2[t * 4 + 2] = pack2(q.z, q.z);
            rp2[t * 4 + 3] = pack2(q.w, q.w);
        }
        #pragma unroll
        for (int kx = 0; kx < 5; kx++) {
            const u64 wv = s_w[(ky * 5 + kx) * 16 + ocl];
            #pragma unroll
            for (int p = 0; p < 24; p++) FMA2(acc[p], rp2[p + kx], wv);
        }
    }

    // per-sample ternarize stats over 18432 values
    float sa = 0.f;
    #pragma unroll
    for (int p = 0; p < 24; p++) {
        const float2 t = unpack2(acc[p]);
        sa += fabsf(t.x) + fabsf(t.y);
    }
    const float tot = block_reduce(sa, s_red, tid, 384);
    const float delta = 0.7f * tot / 18432.f;

    float ms = 0.f, ct = 0.f;
    #pragma unroll
    for (int p = 0; p < 24; p++) {
        const float2 t = unpack2(acc[p]);
        float a = fabsf(t.x); if (a > delta) { ms += a; ct += 1.f; }
        a = fabsf(t.y);       if (a > delta) { ms += a; ct += 1.f; }
    }
    const float2 mc = block_reduce2(ms, ct, s_red, tid, 384);
    const float alpha = mc.x / mc.y;

    const float g0 = bng[ocl] * BN_INV, b0 = bnb[ocl];
    const float g1 = bng[ocl + 16] * BN_INV, b1 = bnb[ocl + 16];

    // ternarize + BN + pool-x -> s_ex
    #pragma unroll
    for (int p = 0; p < 12; p++) {
        const float2 ta = unpack2(acc[2 * p]);
        const float2 tb = unpack2(acc[2 * p + 1]);
        const float mlo = fmaxf(fmaf(ternv(ta.x, delta, alpha), g0, b0),
                                fmaf(ternv(tb.x, delta, alpha), g0, b0));
        const float mhi = fmaxf(fmaf(ternv(ta.y, delta, alpha), g1, b1),
                                fmaf(ternv(tb.y, delta, alpha), g1, b1));
        s_ex[(oy * 12 + p) * 33 + ocl]      = mlo;
        s_ex[(oy * 12 + p) * 33 + ocl + 16] = mhi;
    }
    __syncthreads();

    // pool-y + relu -> g_h1 [s][32][12][12]
    for (int i = tid; i < 4608; i += 384) {
        const int oc = i / 144, r = i % 144, py = r / 12, px = r % 12;
        const float m = fmaxf(s_ex[((2 * py) * 12 + px) * 33 + oc],
                              s_ex[((2 * py + 1) * 12 + px) * 33 + oc]);
        g_h1[s * 4608 + i] = fmaxf(m, 0.f);
    }
}

// ============================================================================
// K2: conv2 + ternarize + BN + maxpool + relu. PERSISTENT, 512 threads.
// Weights (204.8KB, paired) staged in smem ONCE; conv output in registers.
// thread = (oy 0..7, xh 0..1, ocl 0..31); accs = 4 ox as f32x2 (ocl, ocl+32).
// ============================================================================
#define K2_SMEM (25600 * 8 + (4608 + 2080 + 64) * 4)

__global__ __launch_bounds__(512) void k2_conv2(
    const float* __restrict__ bias, const float* __restrict__ bng,
    const float* __restrict__ bnb)
{
    extern __shared__ char smraw[];
    u64*   s_w   = (u64*)smraw;                      // 25600 pairs
    float* s_in  = (float*)(smraw + 25600 * 8);      // 4608
    float* s_ex  = s_in + 4608;                      // [32][65]
    float* s_red = s_ex + 2080;                      // 64

    const int tid = threadIdx.x;
    const int ocl = tid & 31;
    const int xh  = (tid >> 5) & 1;
    const int oy  = tid >> 6;        // 0..7, warp-uniform

    for (int i = tid; i < 25600; i += 512) s_w[i] = g_w2p[i];

    const u64 bb = pack2(bias[ocl], bias[ocl + 32]);
    const float g0 = bng[ocl] * BN_INV, b0 = bnb[ocl];
    const float g1 = bng[ocl + 32] * BN_INV, b1 = bnb[ocl + 32];

    for (int s = blockIdx.x; s < BATCH; s += gridDim.x) {
        __syncthreads();   // s_in/s_ex safe to overwrite
        const float* hin = g_h1 + s * 4608;
        for (int i = tid; i < 4608; i += 512) s_in[i] = hin[i];
        __syncthreads();

        u64 acc[4];
        #pragma unroll
        for (int j = 0; j < 4; j++) acc[j] = bb;

        for (int ic = 0; ic < 32; ic++) {
            #pragma unroll
            for (int ky = 0; ky < 5; ky++) {
                const float* rp = s_in + ic * 144 + (oy + ky) * 12 + xh * 4;
                const float4 q0 = *(const float4*)(rp);
                const float4 q1 = *(const float4*)(rp + 4);
                u64 rp2[8];
                rp2[0] = pack2(q0.x, q0.x); rp2[1] = pack2(q0.y, q0.y);
                rp2[2] = pack2(q0.z, q0.z); rp2[3] = pack2(q0.w, q0.w);
                rp2[4] = pack2(q1.x, q1.x); rp2[5] = pack2(q1.y, q1.y);
                rp2[6] = pack2(q1.z, q1.z); rp2[7] = pack2(q1.w, q1.w);
                #pragma unroll
                for (int kx = 0; kx < 5; kx++) {
                    const u64 wv = s_w[(ic * 25 + ky * 5 + kx) * 32 + ocl];
                    #pragma unroll
                    for (int j = 0; j < 4; j++) FMA2(acc[j], rp2[j + kx], wv);
                }
            }
        }

        // ternarize stats over 4096 values
        float sa = 0.f;
        #pragma unroll
        for (int j = 0; j < 4; j++) {
            const float2 t = unpack2(acc[j]);
            sa += fabsf(t.x) + fabsf(t.y);
        }
        const float tot = block_reduce(sa, s_red, tid, 512);
        const float delta = 0.7f * tot / 4096.f;

        float ms = 0.f, ct = 0.f;
        #pragma unroll
        for (int j = 0; j < 4; j++) {
            const float2 t = unpack2(acc[j]);
            float a = fabsf(t.x); if (a > delta) { ms += a; ct += 1.f; }
            a = fabsf(t.y);       if (a > delta) { ms += a; ct += 1.f; }
        }
        const float2 mc = block_reduce2(ms, ct, s_red, tid, 512);
        const float alpha = mc.x / mc.y;

        // ternarize + BN + pool-x -> s_ex
        #pragma unroll
        for (int p = 0; p < 2; p++) {
            const float2 ta = unpack2(acc[2 * p]);
            const float2 tb = unpack2(acc[2 * p + 1]);
            const float mlo = fmaxf(fmaf(ternv(ta.x, delta, alpha), g0, b0),
                                    fmaf(ternv(tb.x, delta, alpha), g0, b0));
            const float mhi = fmaxf(fmaf(ternv(ta.y, delta, alpha), g1, b1),
                                    fmaf(ternv(tb.y, delta, alpha), g1, b1));
            const int px = xh * 2 + p;
            s_ex[(oy * 4 + px) * 65 + ocl]      = mlo;
            s_ex[(oy * 4 + px) * 65 + ocl + 32] = mhi;
        }
        __syncthreads();

        // pool-y + relu -> g_h2 [s][1024]
        for (int i = tid; i < 1024; i += 512) {
            const int oc = i >> 4, r = i & 15, py = r >> 2, px = r & 3;
            const float m = fmaxf(s_ex[((2 * py) * 4 + px) * 65 + oc],
                                  s_ex[((2 * py + 1) * 4 + px) * 65 + oc]);
            g_h2[s * 1024 + i] = fmaxf(m, 0.f);
        }
    }
}

// ============================================================================
// K3: fc1 GEMM  g_fc1[2048,512] = g_h2 @ fc1_w^T + b. 64x64 tile, f32x2.
// ============================================================================
__global__ __launch_bounds__(256) void k3_fc1(
    const float* __restrict__ Wf, const float* __restrict__ bf)
{
    __shared__ float As[16 * 68];
    __shared__ float Bs[16 * 68];

    const int tid = threadIdx.x;
    const int tx = tid & 15, ty = tid >> 4;
    const int bn = blockIdx.x, bm = blockIdx.y;

    const float* Ap = g_h2 + (size_t)(bm * 64) * 1024;
    const float* Bp = Wf   + (size_t)(bn * 64) * 1024;

    const int lr = tid >> 2;
    const int lk = (tid & 3) * 4;

    u64 acc[4][2];
    #pragma unroll
    for (int i = 0; i < 4; i++) { acc[i][0] = 0ull; acc[i][1] = 0ull; }

    for (int k0 = 0; k0 < 1024; k0 += 16) {
        const float4 a = *(const float4*)(Ap + lr * 1024 + k0 + lk);
        const float4 b = *(const float4*)(Bp + lr * 1024 + k0 + lk);
        __syncthreads();
        As[(lk + 0) * 68 + lr] = a.x; As[(lk + 1) * 68 + lr] = a.y;
        As[(lk + 2) * 68 + lr] = a.z; As[(lk + 3) * 68 + lr] = a.w;
        Bs[(lk + 0) * 68 + lr] = b.x; Bs[(lk + 1) * 68 + lr] = b.y;
        Bs[(lk + 2) * 68 + lr] = b.z; Bs[(lk + 3) * 68 + lr] = b.w;
        __syncthreads();
        #pragma unroll
        for (int kk = 0; kk < 16; kk++) {
            const float4 av = *(const float4*)(&As[kk * 68 + ty * 4]);
            const float4 bv = *(const float4*)(&Bs[kk * 68 + tx * 4]);
            const u64 bp0 = pack2(bv.x, bv.y);
            const u64 bp1 = pack2(bv.z, bv.w);
            const u64 a0 = pack2(av.x, av.x);
            const u64 a1 = pack2(av.y, av.y);
            const u64 a2 = pack2(av.z, av.z);
            const u64 a3 = pack2(av.w, av.w);
            FMA2(acc[0][0], a0, bp0); FMA2(acc[0][1], a0, bp1);
            FMA2(acc[1][0], a1, bp0); FMA2(acc[1][1], a1, bp1);
            FMA2(acc[2][0], a2, bp0); FMA2(acc[2][1], a2, bp1);
            FMA2(acc[3][0], a3, bp0); FMA2(acc[3][1], a3, bp1);
        }
    }

    const int n0 = bn * 64 + tx * 4;
    const float4 bia = *(const float4*)(bf + n0);
    #pragma unroll
    for (int i = 0; i < 4; i++) {
        const int m = bm * 64 + ty * 4 + i;
        const float2 r0 = unpack2(acc[i][0]);
        const float2 r1 = unpack2(acc[i][1]);
        float4 o;
        o.x = r0.x + bia.x; o.y = r0.y + bia.y;
        o.z = r1.x + bia.z; o.w = r1.y + bia.w;
        *(float4*)(g_fc1 + (size_t)m * 512 + n0) = o;
    }
}

// ============================================================================
// K4: ternarize(512)+relu + fc2 + ternarize(10). 1 warp/sample, 8 samples/CTA.
// ============================================================================
__global__ __launch_bounds__(256) void k4_fc2(
    const float* __restrict__ W2, const float* __restrict__ b2,
    float* __restrict__ out)
{
    __shared__ float s_w2[5120];
    __shared__ float s_b2[10];

    const int tid = threadIdx.x;
    for (int i = tid; i < 5120; i += 256) s_w2[i] = W2[i];
    if (tid < 10) s_b2[tid] = b2[tid];
    __syncthreads();

    const int lane = tid & 31, warp = tid >> 5;
    const int s = blockIdx.x * 8 + warp;
    const float* hr = g_fc1 + (size_t)s * 512;

    float h[16];
    #pragma unroll
    for (int k = 0; k < 16; k++) h[k] = hr[lane + 32 * k];

    float sa = 0.f;
    #pragma unroll
    for (int k = 0; k < 16; k++) sa += fabsf(h[k]);
    #pragma unroll
    for (int o = 16; o > 0; o >>= 1) sa += __shfl_xor_sync(0xffffffffu, sa, o);
    const float delta = 0.7f * sa / 512.f;

    float ms = 0.f, ct = 0.f;
    #pragma unroll
    for (int k = 0; k < 16; k++) {
        const float a = fabsf(h[k]);
        if (a > delta) { ms += a; ct += 1.f; }
    }
    #pragma unroll
    for (int o = 16; o > 0; o >>= 1) {
        ms += __shfl_xor_sync(0xffffffffu, ms, o);
        ct += __shfl_xor_sync(0xffffffffu, ct, o);
    }
    const float alpha = ms / ct;

    #pragma unroll
    for (int k = 0; k < 16; k++) h[k] = fmaxf(ternv(h[k], delta, alpha), 0.f);

    float pj[10];
    #pragma unroll
    for (int j = 0; j < 10; j++) {
        float p = 0.f;
        #pragma unroll
        for (int k = 0; k < 16; k++)
            p = fmaf(h[k], s_w2[j * 512 + lane + 32 * k], p);
        #pragma unroll
        for (int o = 16; o > 0; o >>= 1) p += __shfl_xor_sync(0xffffffffu, p, o);
        pj[j] = p + s_b2[j];
    }

    // final row-10 ternarize (all lanes compute redundantly)
    float sa2 = 0.f;
    #pragma unroll
    for (int j = 0; j < 10; j++) sa2 += fabsf(pj[j]);
    const float d2 = 0.7f * sa2 / 10.f;
    float ms2 = 0.f, c2 = 0.f;
    #pragma unroll
    for (int j = 0; j < 10; j++) {
        const float a = fabsf(pj[j]);
        if (a > d2) { ms2 += a; c2 += 1.f; }
    }
    const float al2 = ms2 / c2;

    if (lane < 10) {
        float v = 0.f;
        #pragma unroll
        for (int j = 0; j < 10; j++) if (lane == j) v = pj[j];
        out[(size_t)s * 10 + lane] = (v > d2) ? al2 : ((v < -d2) ? -al2 : 0.f);
    }
}

// ============================================================================
extern "C" void kernel_launch(void* const* d_in, const int* in_sizes, int n_in,
                              void* d_out, int out_size)
{
    const float* x       = (const float*)d_in[0];
    const float* conv1_w = (const float*)d_in[1];
    const float* conv1_b = (const float*)d_in[2];
    const float* bn1_g   = (const float*)d_in[3];
    const float* bn1_b   = (const float*)d_in[4];
    const float* conv2_w = (const float*)d_in[5];
    const float* conv2_b = (const float*)d_in[6];
    const float* bn2_g   = (const float*)d_in[7];
    const float* bn2_b   = (const float*)d_in[8];
    const float* fc1_w   = (const float*)d_in[9];
    const float* fc1_b   = (const float*)d_in[10];
    const float* fc2_w   = (const float*)d_in[11];
    const float* fc2_b   = (const float*)d_in[12];
    float* out = (float*)d_out;

    int nsm = 148;
    cudaDeviceGetAttribute(&nsm, cudaDevAttrMultiProcessorCount, 0);
    if (nsm <= 0) nsm = 148;

    cudaFuncSetAttribute(k2_conv2, cudaFuncAttributeMaxDynamicSharedMemorySize, K2_SMEM);

    k0_pack_w2<<<100, 256>>>(conv2_w);
    k1_conv1<<<BATCH, 384>>>(x, conv1_w, conv1_b, bn1_g, bn1_b);
    k2_conv2<<<nsm, 512, K2_SMEM>>>(conv2_b, bn2_g, bn2_b);
    k3_fc1<<<dim3(8, 32), 256>>>(fc1_w, fc1_b);
    k4_fc2<<<256, 256>>>(fc2_w, fc2_b, out);
}